// round 1
// baseline (speedup 1.0000x reference)
#include <cuda_runtime.h>
#include <cuda_bf16.h>

// Problem constants (fixed by the reference)
#define BQ    2
#define NPTS  8192
#define MPTS  8192
#define GQ    256
#define XMINF (-35.0f)
#define CELLW (0.2734375f)   // 70/256, exactly representable

#define KT     256   // threads per block in knn kernel (= rows per block)
#define SPLIT  16    // j-dimension split across blocks
#define JTILE  128   // j points staged in smem per tile

// -------- scratch (device globals; no allocations allowed) --------
__device__ unsigned long long g_best_x[BQ * NPTS]; // packed (dist_bits<<32)|j
__device__ unsigned long long g_best_y[BQ * MPTS]; // packed (dist_bits<<32)|i (index unused)
__device__ int    g_grid[BQ * GQ * GQ];            // packed (n<<1)|label, -1 = empty
__device__ double g_sum;
__device__ int    g_cnt;

// -------- init: reset all scratch every launch (graph-replay safe) --------
__global__ void init_kernel() {
    int t = blockIdx.x * blockDim.x + threadIdx.x;
    if (t < BQ * GQ * GQ) g_grid[t] = -1;
    if (t < BQ * NPTS)    g_best_x[t] = 0xFFFFFFFFFFFFFFFFULL;
    if (t < BQ * MPTS)    g_best_y[t] = 0xFFFFFFFFFFFFFFFFULL;
    if (t == 0) { g_sum = 0.0; g_cnt = 0; }
}

// -------- brute-force 1-NN (L1), X rows vs Y cols --------
// One thread owns one X row; blockIdx.y selects a chunk of Y of size MPTS/SPLIT.
// Partial mins merged via packed 64-bit atomicMin -> min dist, tie -> min index
// (matches jnp.argmin first-occurrence semantics).
__global__ void knn_kernel(const float* __restrict__ X,
                           const float* __restrict__ Y,
                           int dir /*0: write g_best_x, 1: write g_best_y*/) {
    const int b = blockIdx.z;
    const int i = blockIdx.x * KT + threadIdx.x;
    const int chunk = blockIdx.y;

    const float* Xb = X + (size_t)b * NPTS * 3;
    const float* Yb = Y + (size_t)b * MPTS * 3;

    const float xi = Xb[i * 3 + 0];
    const float yi = Xb[i * 3 + 1];
    const float zi = Xb[i * 3 + 2];

    float bd = 3.4e38f;
    int   bj = 0;

    __shared__ float sy[JTILE * 3];

    const int CHUNK = MPTS / SPLIT;
    const int j0 = chunk * CHUNK;

    for (int jt = 0; jt < CHUNK; jt += JTILE) {
        __syncthreads();
        // cooperative coalesced stage of JTILE points (384 floats)
        for (int t = threadIdx.x; t < JTILE * 3; t += KT)
            sy[t] = Yb[(size_t)(j0 + jt) * 3 + t];
        __syncthreads();

        #pragma unroll 16
        for (int jj = 0; jj < JTILE; jj++) {
            // same fp32 op order as the reference: (|dx|+|dy|)+|dz|
            float d = fabsf(xi - sy[jj * 3 + 0]) + fabsf(yi - sy[jj * 3 + 1]);
            d += fabsf(zi - sy[jj * 3 + 2]);
            if (d < bd) { bd = d; bj = jt + jj; }
        }
    }

    unsigned long long key =
        ((unsigned long long)__float_as_uint(bd) << 32) | (unsigned int)(j0 + bj);
    unsigned long long* best = dir ? g_best_y : g_best_x;
    atomicMin(&best[b * NPTS + i], key);
}

// -------- per-point epilogue: classify, gather p_j, scatter label into grid --------
// Last-write-wins (reference scatter order = increasing n) replicated via
// atomicMax on (n<<1)|label : largest n wins, its label is the LSB.
__global__ void epilogue_kernel(const float* __restrict__ pj,
                                const float* __restrict__ flow_err,
                                const int*  __restrict__ nf) {
    int t = blockIdx.x * blockDim.x + threadIdx.x; // = b*NPTS + n
    if (t >= BQ * NPTS) return;
    int b = t / NPTS;
    int n = t - b * NPTS;

    unsigned long long kx = g_best_x[t];
    unsigned long long ky = g_best_y[t];
    float chx = __uint_as_float((unsigned int)(kx >> 32));
    float chy = __uint_as_float((unsigned int)(ky >> 32));
    int   jr  = (int)(kx & 0xFFFFFFFFu);

    float rigid = (chx + chy) * 0.5f;          // same op order as reference
    bool  dyn   = flow_err[t] > rigid;
    int   idx   = dyn ? nf[t] : jr;
    int   label = dyn ? 1 : 0;

    const float* P = pj + ((size_t)b * MPTS + idx) * 3;
    float px = P[0], py = P[1];

    // IEEE fp32 divide to match XLA exactly (immune to --use_fast_math)
    int gx = (int)__fdiv_rn(px - XMINF, CELLW);
    int gy = (int)__fdiv_rn(py - XMINF, CELLW);
    gx = min(max(gx, 0), GQ - 1);
    gy = min(max(gy, 0), GQ - 1);

    atomicMax(&g_grid[(b * GQ + gx) * GQ + gy], (n << 1) | label);
}

// -------- masked cross-entropy over grid cells --------
__global__ void loss_kernel(const float* __restrict__ mos) {
    int t = blockIdx.x * blockDim.x + threadIdx.x;
    float s = 0.0f;
    int   c = 0;
    if (t < BQ * GQ * GQ) {
        int v = g_grid[t];
        if (v >= 0) {
            int label = v & 1;
            int b     = t / (GQ * GQ);
            int cell  = t - b * GQ * GQ;
            const float* Mb = mos + (size_t)b * 2 * GQ * GQ;
            float m0 = Mb[cell];
            float m1 = Mb[GQ * GQ + cell];
            float mx  = fmaxf(m0, m1);
            float lse = mx + logf(expf(m0 - mx) + expf(m1 - mx));
            s = lse - (label ? m1 : m0);   // = -log_softmax[label]
            c = 1;
        }
    }
    __shared__ float ss[256];
    __shared__ int   sc[256];
    ss[threadIdx.x] = s;
    sc[threadIdx.x] = c;
    __syncthreads();
    for (int o = 128; o > 0; o >>= 1) {
        if (threadIdx.x < o) {
            ss[threadIdx.x] += ss[threadIdx.x + o];
            sc[threadIdx.x] += sc[threadIdx.x + o];
        }
        __syncthreads();
    }
    if (threadIdx.x == 0) {
        atomicAdd(&g_sum, (double)ss[0]);
        atomicAdd(&g_cnt, sc[0]);
    }
}

__global__ void finalize_kernel(float* out) {
    int cnt = g_cnt;
    if (cnt < 1) cnt = 1;
    out[0] = (float)(g_sum / (double)cnt);
}

// -------- launch --------
extern "C" void kernel_launch(void* const* d_in, const int* in_sizes, int n_in,
                              void* d_out, int out_size) {
    const float* p_i  = (const float*)d_in[0]; // (B,N,3)
    const float* mos  = (const float*)d_in[1]; // (B,2,G,G)
    const float* p_j  = (const float*)d_in[2]; // (B,M,3)
    const float* ferr = (const float*)d_in[3]; // (B,N)
    const int*   nf   = (const int*)d_in[4];   // (B,N,1)
    float* out = (float*)d_out;

    init_kernel<<<(BQ * GQ * GQ + 255) / 256, 256>>>();

    dim3 kg(NPTS / KT, SPLIT, BQ);
    knn_kernel<<<kg, KT>>>(p_i, p_j, 0); // cham_x + nearest_rigid
    knn_kernel<<<kg, KT>>>(p_j, p_i, 1); // cham_y

    epilogue_kernel<<<(BQ * NPTS + 255) / 256, 256>>>(p_j, ferr, nf);
    loss_kernel<<<(BQ * GQ * GQ + 255) / 256, 256>>>(mos);
    finalize_kernel<<<1, 1>>>(out);
}

// round 2
// speedup vs baseline: 1.4469x; 1.4469x over previous
#include <cuda_runtime.h>
#include <cuda_bf16.h>

// Problem constants (fixed by the reference)
#define BQ    2
#define NPTS  8192
#define MPTS  8192
#define GQ    256
#define XMINF (-35.0f)
#define CELLW (0.2734375f)   // 70/256, exactly representable

// Fused-KNN tiling
#define KT    256            // threads per block
#define RROWS 8              // i-rows per thread (register tile)
#define TI    (KT * RROWS)   // 2048 i-rows per block
#define JCH   256            // j-cols per block (staged once in smem)

// -------- scratch (device globals; no allocations allowed) --------
__device__ unsigned long long g_best_x[BQ * NPTS]; // packed (dist_bits<<32)|j : row-min+argmin of D
__device__ unsigned int       g_ymin[BQ * MPTS];   // float bits of col-min of D (cham_y)
__device__ int    g_grid[BQ * GQ * GQ];            // packed (n<<1)|label, -1 = empty
__device__ double g_sum;
__device__ int    g_cnt;

// -------- init: reset all scratch every launch (graph-replay safe) --------
__global__ void init_kernel() {
    int t = blockIdx.x * blockDim.x + threadIdx.x;
    if (t < BQ * GQ * GQ) g_grid[t] = -1;
    if (t < BQ * NPTS)    g_best_x[t] = 0xFFFFFFFFFFFFFFFFULL;
    if (t < BQ * MPTS)    g_ymin[t]   = 0xFFFFFFFFu;
    if (t == 0) { g_sum = 0.0; g_cnt = 0; }
}

// -------- fused brute-force 1-NN (L1) --------
// One pass over D[i][j] = |xi-xj|+|yi-yj|+|zi-zj| computing BOTH
//   row-min+argmin (cham_x, nearest_rigid)  and  col-min (cham_y, argmin unused).
// Each thread register-tiles RROWS i-rows; j staged SoA in smem and consumed
// two-at-a-time via LDS.64 + packed add.rn.f32x2 against pre-negated query pairs.
// Col-min: lane-local FMNMX over RROWS rows, warp redux.min.u32 (positive float
// bits are order-isomorphic to uint), single REDG per column per warp.
__global__ void __launch_bounds__(KT, 2)
fused_knn_kernel(const float* __restrict__ p_i, const float* __restrict__ p_j) {
    const int b     = blockIdx.z;
    const int iBase = blockIdx.y * TI;
    const int j0    = blockIdx.x * JCH;

    const float* Xb = p_i + (size_t)b * NPTS * 3;
    const float* Yb = p_j + (size_t)b * MPTS * 3;

    __shared__ __align__(16) float sx[JCH];
    __shared__ __align__(16) float sy[JCH];
    __shared__ __align__(16) float sz[JCH];

    // stage the j-tile, coalesced global reads, SoA transpose into smem
    for (int t = threadIdx.x; t < JCH * 3; t += KT) {
        int j = t / 3;
        int c = t - 3 * j;
        float v = Yb[(size_t)j0 * 3 + t];
        if (c == 0) sx[j] = v; else if (c == 1) sy[j] = v; else sz[j] = v;
    }

    // load queries, pre-negate and duplicate into f32x2 pairs
    unsigned long long nx[RROWS], ny[RROWS], nz[RROWS];
    float bd[RROWS];
    int   bj[RROWS];
    #pragma unroll
    for (int k = 0; k < RROWS; k++) {
        int row = iBase + threadIdx.x + k * KT;
        float x = Xb[row * 3 + 0];
        float y = Xb[row * 3 + 1];
        float z = Xb[row * 3 + 2];
        float mx = -x, my = -y, mz = -z;
        asm("mov.b64 %0, {%1,%2};" : "=l"(nx[k]) : "f"(mx), "f"(mx));
        asm("mov.b64 %0, {%1,%2};" : "=l"(ny[k]) : "f"(my), "f"(my));
        asm("mov.b64 %0, {%1,%2};" : "=l"(nz[k]) : "f"(mz), "f"(mz));
        bd[k] = 3.4e38f;
        bj[k] = 0;
    }
    __syncthreads();

    const int lane0 = ((threadIdx.x & 31) == 0);

    #pragma unroll 2
    for (int s = 0; s < JCH; s += 2) {
        // warp-uniform broadcast loads of two j-points (SoA, 8B aligned)
        unsigned long long vx = *reinterpret_cast<const unsigned long long*>(&sx[s]);
        unsigned long long vy = *reinterpret_cast<const unsigned long long*>(&sy[s]);
        unsigned long long vz = *reinterpret_cast<const unsigned long long*>(&sz[s]);

        float cmin0 = 3.4e38f, cmin1 = 3.4e38f;

        #pragma unroll
        for (int k = 0; k < RROWS; k++) {
            unsigned long long tx, ty, tz;
            asm("add.rn.f32x2 %0, %1, %2;" : "=l"(tx) : "l"(vx), "l"(nx[k]));
            asm("add.rn.f32x2 %0, %1, %2;" : "=l"(ty) : "l"(vy), "l"(ny[k]));
            asm("add.rn.f32x2 %0, %1, %2;" : "=l"(tz) : "l"(vz), "l"(nz[k]));
            float txl, txh, tyl, tyh, tzl, tzh;
            asm("mov.b64 {%0,%1}, %2;" : "=f"(txl), "=f"(txh) : "l"(tx));
            asm("mov.b64 {%0,%1}, %2;" : "=f"(tyl), "=f"(tyh) : "l"(ty));
            asm("mov.b64 {%0,%1}, %2;" : "=f"(tzl), "=f"(tzh) : "l"(tz));
            // same fp32 op order as the reference: (|dx|+|dy|)+|dz|
            float d0 = fabsf(txl) + fabsf(tyl);  d0 += fabsf(tzl);
            float d1 = fabsf(txh) + fabsf(tyh);  d1 += fabsf(tzh);
            // row-min + first-occurrence argmin (strict <)
            if (d0 < bd[k]) { bd[k] = d0; bj[k] = j0 + s; }
            if (d1 < bd[k]) { bd[k] = d1; bj[k] = j0 + s + 1; }
            // col-min contributions
            cmin0 = fminf(cmin0, d0);
            cmin1 = fminf(cmin1, d1);
        }

        // warp-wide column min (positive floats: uint bit order == float order)
        unsigned u0 = __reduce_min_sync(0xFFFFFFFFu, __float_as_uint(cmin0));
        unsigned u1 = __reduce_min_sync(0xFFFFFFFFu, __float_as_uint(cmin1));
        if (lane0) {
            atomicMin(&g_ymin[b * MPTS + j0 + s],     u0);
            atomicMin(&g_ymin[b * MPTS + j0 + s + 1], u1);
        }
    }

    // merge this block's row partial mins; packed key => min dist, tie -> min j
    #pragma unroll
    for (int k = 0; k < RROWS; k++) {
        int row = iBase + threadIdx.x + k * KT;
        unsigned long long key =
            ((unsigned long long)__float_as_uint(bd[k]) << 32) | (unsigned int)bj[k];
        atomicMin(&g_best_x[b * NPTS + row], key);
    }
}

// -------- per-point epilogue: classify, gather p_j, scatter label into grid --------
// Last-write-wins (reference scatter order = increasing n) replicated via
// atomicMax on (n<<1)|label : largest n wins, its label is the LSB.
__global__ void epilogue_kernel(const float* __restrict__ pj,
                                const float* __restrict__ flow_err,
                                const int*  __restrict__ nf) {
    int t = blockIdx.x * blockDim.x + threadIdx.x; // = b*NPTS + n
    if (t >= BQ * NPTS) return;
    int b = t / NPTS;
    int n = t - b * NPTS;

    unsigned long long kx = g_best_x[t];
    float chx = __uint_as_float((unsigned int)(kx >> 32));
    float chy = __uint_as_float(g_ymin[t]);
    int   jr  = (int)(kx & 0xFFFFFFFFu);

    float rigid = (chx + chy) * 0.5f;          // same op order as reference
    bool  dyn   = flow_err[t] > rigid;
    int   idx   = dyn ? nf[t] : jr;
    int   label = dyn ? 1 : 0;

    const float* P = pj + ((size_t)b * MPTS + idx) * 3;
    float px = P[0], py = P[1];

    // IEEE fp32 divide to match XLA exactly (immune to --use_fast_math)
    int gx = (int)__fdiv_rn(px - XMINF, CELLW);
    int gy = (int)__fdiv_rn(py - XMINF, CELLW);
    gx = min(max(gx, 0), GQ - 1);
    gy = min(max(gy, 0), GQ - 1);

    atomicMax(&g_grid[(b * GQ + gx) * GQ + gy], (n << 1) | label);
}

// -------- masked cross-entropy over grid cells --------
__global__ void loss_kernel(const float* __restrict__ mos) {
    int t = blockIdx.x * blockDim.x + threadIdx.x;
    float s = 0.0f;
    int   c = 0;
    if (t < BQ * GQ * GQ) {
        int v = g_grid[t];
        if (v >= 0) {
            int label = v & 1;
            int b     = t / (GQ * GQ);
            int cell  = t - b * GQ * GQ;
            const float* Mb = mos + (size_t)b * 2 * GQ * GQ;
            float m0 = Mb[cell];
            float m1 = Mb[GQ * GQ + cell];
            float mx  = fmaxf(m0, m1);
            float lse = mx + logf(expf(m0 - mx) + expf(m1 - mx));
            s = lse - (label ? m1 : m0);   // = -log_softmax[label]
            c = 1;
        }
    }
    __shared__ float ss[256];
    __shared__ int   sc[256];
    ss[threadIdx.x] = s;
    sc[threadIdx.x] = c;
    __syncthreads();
    for (int o = 128; o > 0; o >>= 1) {
        if (threadIdx.x < o) {
            ss[threadIdx.x] += ss[threadIdx.x + o];
            sc[threadIdx.x] += sc[threadIdx.x + o];
        }
        __syncthreads();
    }
    if (threadIdx.x == 0) {
        atomicAdd(&g_sum, (double)ss[0]);
        atomicAdd(&g_cnt, sc[0]);
    }
}

__global__ void finalize_kernel(float* out) {
    int cnt = g_cnt;
    if (cnt < 1) cnt = 1;
    out[0] = (float)(g_sum / (double)cnt);
}

// -------- launch --------
extern "C" void kernel_launch(void* const* d_in, const int* in_sizes, int n_in,
                              void* d_out, int out_size) {
    const float* p_i  = (const float*)d_in[0]; // (B,N,3)
    const float* mos  = (const float*)d_in[1]; // (B,2,G,G)
    const float* p_j  = (const float*)d_in[2]; // (B,M,3)
    const float* ferr = (const float*)d_in[3]; // (B,N)
    const int*   nf   = (const int*)d_in[4];   // (B,N,1)
    float* out = (float*)d_out;

    init_kernel<<<(BQ * GQ * GQ + 255) / 256, 256>>>();

    dim3 kg(MPTS / JCH, NPTS / TI, BQ);   // (32, 4, 2) = 256 blocks
    fused_knn_kernel<<<kg, KT>>>(p_i, p_j);

    epilogue_kernel<<<(BQ * NPTS + 255) / 256, 256>>>(p_j, ferr, nf);
    loss_kernel<<<(BQ * GQ * GQ + 255) / 256, 256>>>(mos);
    finalize_kernel<<<1, 1>>>(out);
}

// round 3
// speedup vs baseline: 1.7296x; 1.1954x over previous
#include <cuda_runtime.h>
#include <cuda_bf16.h>

// Problem constants (fixed by the reference)
#define BQ    2
#define NPTS  8192
#define MPTS  8192
#define GQ    256
#define XMINF (-35.0f)
#define CELLW (0.2734375f)   // 70/256, exactly representable

// Spatial bucket grid for exact 1-NN
#define GS      16
#define GS3     (GS * GS * GS)
#define CELLSZ  4.25f          // 68/16, exact in fp32
#define INVCELL (1.0f / 4.25f)

// -------- scratch (device globals; no allocations allowed) --------
__device__ int    g_ccnt  [2 * BQ * GS3];   // per (src,b) cell counts
__device__ int    g_offs  [2 * BQ * GS3];   // exclusive prefix offsets
__device__ int    g_cursor[2 * BQ * GS3];   // scatter cursors (copy of offs)
__device__ int    g_cellid[2 * BQ * 8192];  // cell id per point
__device__ float4 g_sorted[2 * BQ * 8192];  // bucketed points (x,y,z,orig_idx)
__device__ unsigned long long g_best_x[BQ * NPTS]; // (dist_bits<<32)|argmin_j
__device__ unsigned long long g_best_y[BQ * MPTS]; // (dist_bits<<32)|argmin_i (idx unused)
__device__ int    g_grid[BQ * GQ * GQ];     // packed (n<<1)|label, -1 = empty
__device__ double g_sum;
__device__ int    g_vcnt;

// -------- init: reset scratch every launch (graph-replay safe) --------
__global__ void init_kernel() {
    int t = blockIdx.x * blockDim.x + threadIdx.x;
    if (t < BQ * GQ * GQ) g_grid[t] = -1;
    if (t < 2 * BQ * GS3) g_ccnt[t] = 0;
    if (t == 0) { g_sum = 0.0; g_vcnt = 0; }
}

__device__ __forceinline__ int cell_coord(float v) {
    int c = (int)((v + 34.0f) * INVCELL);
    return min(max(c, 0), GS - 1);
}

// -------- histogram: count points per cell, remember each point's cell --------
__global__ void hist_kernel(const float* __restrict__ p_i,
                            const float* __restrict__ p_j) {
    int t = blockIdx.x * blockDim.x + threadIdx.x;   // [src][b][n]
    int n = t & 8191, b = (t >> 13) & 1, src = t >> 14;
    const float* P = (src ? p_j : p_i) + ((size_t)b * 8192 + n) * 3;
    int cx = cell_coord(P[0]);
    int cy = cell_coord(P[1]);
    int cz = cell_coord(P[2]);
    int cell = (cz * GS + cy) * GS + cx;
    g_cellid[t] = cell;
    atomicAdd(&g_ccnt[(src * BQ + b) * GS3 + cell], 1);
}

// -------- exclusive prefix scan over the 4096 counts of each (src,b) --------
__global__ void scan_kernel() {
    const int base = blockIdx.x * GS3;   // 4 combos
    const int lane = threadIdx.x & 31, warp = threadIdx.x >> 5;
    __shared__ int wsum[16];

    int v[8]; int s = 0;
    #pragma unroll
    for (int k = 0; k < 8; k++) { v[k] = g_ccnt[base + threadIdx.x * 8 + k]; s += v[k]; }

    int inc = s;
    #pragma unroll
    for (int o = 1; o < 32; o <<= 1) {
        int x = __shfl_up_sync(0xFFFFFFFFu, inc, o);
        if (lane >= o) inc += x;
    }
    if (lane == 31) wsum[warp] = inc;
    __syncthreads();
    if (warp == 0 && lane < 16) {
        int w = wsum[lane];
        #pragma unroll
        for (int o = 1; o < 16; o <<= 1) {
            int x = __shfl_up_sync(0xFFFFu, w, o);
            if (lane >= o) w += x;
        }
        wsum[lane] = w;
    }
    __syncthreads();
    int excl = inc - s + (warp ? wsum[warp - 1] : 0);
    #pragma unroll
    for (int k = 0; k < 8; k++) {
        int idx = base + threadIdx.x * 8 + k;
        g_offs[idx] = excl;
        g_cursor[idx] = excl;
        excl += v[k];
    }
}

// -------- scatter points into bucket order --------
__global__ void scatter_kernel(const float* __restrict__ p_i,
                               const float* __restrict__ p_j) {
    int t = blockIdx.x * blockDim.x + threadIdx.x;
    int n = t & 8191, b = (t >> 13) & 1, src = t >> 14;
    const float* P = (src ? p_j : p_i) + ((size_t)b * 8192 + n) * 3;
    int cell = g_cellid[t];
    int pos = atomicAdd(&g_cursor[(src * BQ + b) * GS3 + cell], 1);
    g_sorted[(src * BQ + b) * 8192 + pos] = make_float4(P[0], P[1], P[2], __int_as_float(n));
}

// -------- exact 1-NN via expanding L1 ring search --------
// One thread per query (in bucket order for warp locality). Result owned by the
// thread -> plain store, no atomics. Packed (dist_bits<<32)|orig_j key min gives
// exact min-dist with first-occurrence (min-j) tie-break, matching jnp.argmin.
// Termination: L1 lower bound of Chebyshev ring r is (r-1)*CELLSZ; break when it
// strictly exceeds best (with small safety margin), so ties are never missed.
__global__ void query_kernel() {
    int t = blockIdx.x * blockDim.x + threadIdx.x;   // [dir][b][q]
    int q = t & 8191, b = (t >> 13) & 1, dir = t >> 14;
    int qsrc = dir;          // dir0: queries p_i vs targets p_j (cham_x)
    int tsrc = 1 - dir;      // dir1: queries p_j vs targets p_i (cham_y)

    float4 Q = g_sorted[(qsrc * BQ + b) * 8192 + q];
    const float qx = Q.x, qy = Q.y, qz = Q.z;
    const int orig = __float_as_int(Q.w);

    const int* offs = &g_offs[(tsrc * BQ + b) * GS3];
    const int* cnts = &g_ccnt[(tsrc * BQ + b) * GS3];
    const float4* __restrict__ T = &g_sorted[(tsrc * BQ + b) * 8192];

    const int qcx = cell_coord(qx), qcy = cell_coord(qy), qcz = cell_coord(qz);

    unsigned long long bestkey = ((unsigned long long)0x7F800000u << 32); // +inf

    for (int r = 0; r < GS; r++) {
        if (r >= 1) {
            float bestd = __uint_as_float((unsigned)(bestkey >> 32));
            if ((float)(r - 1) * CELLSZ - 1e-3f > bestd) break;
        }
        int z0 = max(qcz - r, 0), z1 = min(qcz + r, GS - 1);
        int y0 = max(qcy - r, 0), y1 = min(qcy + r, GS - 1);
        int x0 = max(qcx - r, 0), x1 = min(qcx + r, GS - 1);
        for (int cz = z0; cz <= z1; cz++) {
            int az = abs(cz - qcz);
            for (int cy = y0; cy <= y1; cy++) {
                int am = max(az, abs(cy - qcy));
                int rowbase = (cz * GS + cy) * GS;
                int p0, p1;
                if (am == r) {
                    // whole x-run is on the shell; cells contiguous -> one range
                    p0 = offs[rowbase + x0];
                    p1 = offs[rowbase + x1] + cnts[rowbase + x1];
                    for (int p = p0; p < p1; p++) {
                        float4 tp = T[p];
                        float d = fabsf(qx - tp.x) + fabsf(qy - tp.y);
                        d += fabsf(qz - tp.z);
                        unsigned long long key =
                            ((unsigned long long)__float_as_uint(d) << 32) |
                            (unsigned)__float_as_int(tp.w);
                        if (key < bestkey) bestkey = key;
                    }
                } else {
                    // only the two x-extremes are on the shell
                    #pragma unroll
                    for (int sgn = 0; sgn < 2; sgn++) {
                        int cx = sgn ? qcx + r : qcx - r;
                        if (cx < 0 || cx > GS - 1) continue;
                        int c = rowbase + cx;
                        p0 = offs[c]; p1 = p0 + cnts[c];
                        for (int p = p0; p < p1; p++) {
                            float4 tp = T[p];
                            float d = fabsf(qx - tp.x) + fabsf(qy - tp.y);
                            d += fabsf(qz - tp.z);
                            unsigned long long key =
                                ((unsigned long long)__float_as_uint(d) << 32) |
                                (unsigned)__float_as_int(tp.w);
                            if (key < bestkey) bestkey = key;
                        }
                    }
                }
            }
        }
    }

    (dir ? g_best_y : g_best_x)[b * 8192 + orig] = bestkey;
}

// -------- per-point epilogue: classify, gather p_j, scatter label into grid --------
// Last-write-wins (reference scatter order = increasing n) replicated via
// atomicMax on (n<<1)|label : largest n wins, its label is the LSB.
__global__ void epilogue_kernel(const float* __restrict__ pj,
                                const float* __restrict__ flow_err,
                                const int*  __restrict__ nf) {
    int t = blockIdx.x * blockDim.x + threadIdx.x; // = b*NPTS + n
    if (t >= BQ * NPTS) return;
    int b = t / NPTS;
    int n = t - b * NPTS;

    unsigned long long kx = g_best_x[t];
    unsigned long long ky = g_best_y[t];
    float chx = __uint_as_float((unsigned)(kx >> 32));
    float chy = __uint_as_float((unsigned)(ky >> 32));
    int   jr  = (int)(kx & 0xFFFFFFFFu);

    float rigid = (chx + chy) * 0.5f;          // same op order as reference
    bool  dyn   = flow_err[t] > rigid;
    int   idx   = dyn ? nf[t] : jr;
    int   label = dyn ? 1 : 0;

    const float* P = pj + ((size_t)b * MPTS + idx) * 3;
    float px = P[0], py = P[1];

    // IEEE fp32 divide to match XLA exactly (immune to --use_fast_math)
    int gx = (int)__fdiv_rn(px - XMINF, CELLW);
    int gy = (int)__fdiv_rn(py - XMINF, CELLW);
    gx = min(max(gx, 0), GQ - 1);
    gy = min(max(gy, 0), GQ - 1);

    atomicMax(&g_grid[(b * GQ + gx) * GQ + gy], (n << 1) | label);
}

// -------- masked cross-entropy over grid cells --------
__global__ void loss_kernel(const float* __restrict__ mos) {
    int t = blockIdx.x * blockDim.x + threadIdx.x;
    float s = 0.0f;
    int   c = 0;
    if (t < BQ * GQ * GQ) {
        int v = g_grid[t];
        if (v >= 0) {
            int label = v & 1;
            int b     = t / (GQ * GQ);
            int cell  = t - b * GQ * GQ;
            const float* Mb = mos + (size_t)b * 2 * GQ * GQ;
            float m0 = Mb[cell];
            float m1 = Mb[GQ * GQ + cell];
            // lse = max + log(1 + e^{-|m0-m1|})
            float lse = fmaxf(m0, m1) + log1pf(__expf(-fabsf(m0 - m1)));
            s = lse - (label ? m1 : m0);   // = -log_softmax[label]
            c = 1;
        }
    }
    // warp then block reduction
    #pragma unroll
    for (int o = 16; o > 0; o >>= 1) {
        s += __shfl_down_sync(0xFFFFFFFFu, s, o);
        c += __shfl_down_sync(0xFFFFFFFFu, c, o);
    }
    __shared__ float ss[8];
    __shared__ int   sc[8];
    int lane = threadIdx.x & 31, warp = threadIdx.x >> 5;
    if (lane == 0) { ss[warp] = s; sc[warp] = c; }
    __syncthreads();
    if (warp == 0) {
        s = (lane < 8) ? ss[lane] : 0.0f;
        c = (lane < 8) ? sc[lane] : 0;
        #pragma unroll
        for (int o = 4; o > 0; o >>= 1) {
            s += __shfl_down_sync(0xFFFFFFFFu, s, o);
            c += __shfl_down_sync(0xFFFFFFFFu, c, o);
        }
        if (lane == 0) {
            atomicAdd(&g_sum, (double)s);
            atomicAdd(&g_vcnt, c);
        }
    }
}

__global__ void finalize_kernel(float* out) {
    int cnt = g_vcnt;
    if (cnt < 1) cnt = 1;
    out[0] = (float)(g_sum / (double)cnt);
}

// -------- launch --------
extern "C" void kernel_launch(void* const* d_in, const int* in_sizes, int n_in,
                              void* d_out, int out_size) {
    const float* p_i  = (const float*)d_in[0]; // (B,N,3)
    const float* mos  = (const float*)d_in[1]; // (B,2,G,G)
    const float* p_j  = (const float*)d_in[2]; // (B,M,3)
    const float* ferr = (const float*)d_in[3]; // (B,N)
    const int*   nf   = (const int*)d_in[4];   // (B,N,1)
    float* out = (float*)d_out;

    init_kernel<<<(BQ * GQ * GQ + 255) / 256, 256>>>();
    hist_kernel<<<(2 * BQ * 8192) / 256, 256>>>(p_i, p_j);
    scan_kernel<<<2 * BQ, 512>>>();
    scatter_kernel<<<(2 * BQ * 8192) / 256, 256>>>(p_i, p_j);
    query_kernel<<<(2 * BQ * 8192) / 256, 256>>>();
    epilogue_kernel<<<(BQ * NPTS + 255) / 256, 256>>>(p_j, ferr, nf);
    loss_kernel<<<(BQ * GQ * GQ + 255) / 256, 256>>>(mos);
    finalize_kernel<<<1, 1>>>(out);
}